// round 1
// baseline (speedup 1.0000x reference)
#include <cuda_runtime.h>

// QuantumLinear: 4-qubit circuit sim, one thread per (batch, circuit) pair.
// B=4096, C=256, NQ=4, L=2. x: (B, 1024) f32, weights: (C, 2, 4) f32,
// out: (B, 1024) f32.
//
// Math: out[b, 4c+q] = <Z_q> of  Ring · RX(w1) · Ring · (prod-state RX(x+w0)|0>)
// (embedding RX(x) and layer-0 RX(w0) fused: RX(a)RX(b) = RX(a+b)).

#define QL_BDIM 256

__global__ __launch_bounds__(QL_BDIM)
void ql_sim_kernel(const float4* __restrict__ x4,
                   const float4* __restrict__ w4,
                   float4* __restrict__ out4,
                   int total)
{
    int t = blockIdx.x * QL_BDIM + threadIdx.x;
    if (t >= total) return;
    int c = t & 255;                      // circuit index (C = 256)

    float4 xv = x4[t];                    // 4 input angles for this (b,c)
    float4 w0 = w4[2 * c];                // layer-0 weights (fused into embed)
    float4 w1 = w4[2 * c + 1];            // layer-1 weights

    float aE[4] = { xv.x + w0.x, xv.y + w0.y, xv.z + w0.z, xv.w + w0.w };
    float aW[4] = { w1.x, w1.y, w1.z, w1.w };

    float cE[4], sE[4], cW[4], sW[4];
#pragma unroll
    for (int q = 0; q < 4; q++) {
        __sincosf(0.5f * aE[q], &sE[q], &cE[q]);
        __sincosf(0.5f * aW[q], &sW[q], &cW[q]);
    }

    // ---- Fused embedding + layer-0 RX: product state ----
    // amp[i] = (-i)^popcount(i) * prod_q (bit_q(i) ? sin : cos)
    // Exact 0.0f literals let ptxas constant-fold the pure-phase structure
    // through the (register-permutation) CNOT ring and into layer-1 RX.
    float ar[16], ai[16];
#pragma unroll
    for (int i = 0; i < 16; i++) {
        float m = 1.0f; int k = 0;
#pragma unroll
        for (int q = 0; q < 4; q++) {
            if ((i >> q) & 1) { m *= sE[q]; k++; }
            else             { m *= cE[q]; }
        }
        int kk = k & 3;   // compile-time after unroll
        ar[i] = (kk == 0) ? m : ((kk == 2) ? -m : 0.0f);
        ai[i] = (kk == 1) ? -m : ((kk == 3) ? m : 0.0f);
    }

    // ---- Ring of CNOTs (layer 0): pure register permutation ----
#pragma unroll
    for (int g = 0; g < 4; g++) {
        int ctrl = g, tgt = (g + 1) & 3;
#pragma unroll
        for (int i = 0; i < 16; i++) {
            if (((i >> ctrl) & 1) && !((i >> tgt) & 1)) {
                int j = i | (1 << tgt);
                float tr = ar[i]; ar[i] = ar[j]; ar[j] = tr;
                float ti = ai[i]; ai[i] = ai[j]; ai[j] = ti;
            }
        }
    }

    // ---- Layer-1 RX on every wire (commuting; order 3,0,1,2 keeps the
    //      pure-real/pure-imag zeros alive longest for constant folding) ----
    const int order[4] = { 3, 0, 1, 2 };
#pragma unroll
    for (int gg = 0; gg < 4; gg++) {
        int q = order[gg];
        float cc = cW[q], ss = sW[q];
#pragma unroll
        for (int i = 0; i < 16; i++) {
            if (!((i >> q) & 1)) {
                int j = i | (1 << q);
                float r0 = ar[i], i0 = ai[i];
                float r1 = ar[j], i1 = ai[j];
                // new0 = c*a0 - i s*a1 ; new1 = -i s*a0 + c*a1
                ar[i] = cc * r0 + ss * i1;
                ai[i] = cc * i0 - ss * r1;
                ar[j] = ss * i0 + cc * r1;
                ai[j] = cc * i1 - ss * r0;
            }
        }
    }

    // ---- Ring of CNOTs (layer 1) ----
#pragma unroll
    for (int g = 0; g < 4; g++) {
        int ctrl = g, tgt = (g + 1) & 3;
#pragma unroll
        for (int i = 0; i < 16; i++) {
            if (((i >> ctrl) & 1) && !((i >> tgt) & 1)) {
                int j = i | (1 << tgt);
                float tr = ar[i]; ar[i] = ar[j]; ar[j] = tr;
                float ti = ai[i]; ai[i] = ai[j]; ai[j] = ti;
            }
        }
    }

    // ---- Measurement: z_q = sum_i |amp[i]|^2 * (1 - 2*bit_q(i)) ----
    float z0 = 0.f, z1 = 0.f, z2 = 0.f, z3 = 0.f;
#pragma unroll
    for (int i = 0; i < 16; i++) {
        float p = ar[i] * ar[i] + ai[i] * ai[i];
        z0 += ((i >> 0) & 1) ? -p : p;
        z1 += ((i >> 1) & 1) ? -p : p;
        z2 += ((i >> 2) & 1) ? -p : p;
        z3 += ((i >> 3) & 1) ? -p : p;
    }

    out4[t] = make_float4(z0, z1, z2, z3);
}

extern "C" void kernel_launch(void* const* d_in, const int* in_sizes, int n_in,
                              void* d_out, int out_size)
{
    const float4* x4 = (const float4*)d_in[0];   // x: (4096, 1024) f32
    const float4* w4 = (const float4*)d_in[1];   // weights: (256, 2, 4) f32
    float4* o4 = (float4*)d_out;                 // out: (4096, 1024) f32

    int total = in_sizes[0] / 4;                 // number of (b,c) sims = 1,048,576
    int grid = (total + QL_BDIM - 1) / QL_BDIM;
    ql_sim_kernel<<<grid, QL_BDIM>>>(x4, w4, o4, total);
}

// round 6
// speedup vs baseline: 2.1068x; 2.1068x over previous
#include <cuda_runtime.h>

// QuantumLinear in CLOSED FORM.
//
// X-basis (H-conjugated) simulation makes all amplitudes pure phases whose
// exponent is a sum of 8 Walsh characters. Propagating the character masks
// through both CNOT rings and summing the readout with
// sum_{s=+-1} cos(A+sB) = 2 cosA cosB collapses each <Z_q> to a product of
// at most 3 cosines, a_q = x_q + w0_q (embedding RX fused with layer-0 RX),
// b_q = w1_q:
//   z0 = 1/2[cos(a1+a3)cos(a0+b3)cos(b1+b2) + cos(a1-a3)cos(a0-b3)cos(b1-b2)]
//   z1 = 1/2 cos(a3)[cos(a0+a2)cos(b0+b1) + cos(a0-a2)cos(b0-b1)]
//   z2 = 1/2 cos(b0)[cos(a1+a3)cos(b1+b2) + cos(a1-a3)cos(b1-b2)]
//   z3 = 1/2[cos(b2+b3)cos(a2+b0)cos(a0+b1) + cos(b2-b3)cos(a2-b0)cos(a0-b1)]
//
// 11 data cosines per sim; 7 weight-only cosines amortized over 4 sims/thread
// (the 4 sims share the circuit index since the stride is a multiple of 256).

#define QL_BDIM 256
#define SPT 4            // sims per thread

__global__ __launch_bounds__(QL_BDIM)
void ql_closed_kernel(const float4* __restrict__ x4,
                      const float4* __restrict__ w4,
                      float4* __restrict__ out4,
                      int nthreads)          // = total_sims / SPT, multiple of 256
{
    int t = blockIdx.x * QL_BDIM + threadIdx.x;
    if (t >= nthreads) return;
    int c = t & 255;                          // circuit index, same for all SPT sims

    float4 w0 = w4[2 * c];
    float4 w1 = w4[2 * c + 1];
    float b0 = w1.x, b1 = w1.y, b2 = w1.z, b3 = w1.w;

    // weight-only constants (1/2 folded in)
    float h12p = 0.5f * __cosf(b1 + b2);
    float h12m = 0.5f * __cosf(b1 - b2);
    float h01p = 0.5f * __cosf(b0 + b1);
    float h01m = 0.5f * __cosf(b0 - b1);
    float cb0  = __cosf(b0);
    float g12p = cb0 * h12p;                  // for z2
    float g12m = cb0 * h12m;
    float h23p = 0.5f * __cosf(b2 + b3);
    float h23m = 0.5f * __cosf(b2 - b3);

#pragma unroll
    for (int s = 0; s < SPT; s++) {
        int idx = t + s * nthreads;           // coalesced across the warp
        float4 xv = x4[idx];
        float a0 = xv.x + w0.x;
        float a1 = xv.y + w0.y;
        float a2 = xv.z + w0.z;
        float a3 = xv.w + w0.w;

        float ca13p = __cosf(a1 + a3);
        float ca13m = __cosf(a1 - a3);

        float c0p = __cosf(a0 + b3);
        float c0m = __cosf(a0 - b3);
        float z0 = fmaf(ca13m * c0m, h12m, (ca13p * c0p) * h12p);

        float ca3  = __cosf(a3);
        float c02p = __cosf(a0 + a2);
        float c02m = __cosf(a0 - a2);
        float z1 = ca3 * fmaf(c02m, h01m, c02p * h01p);

        float z2 = fmaf(ca13m, g12m, ca13p * g12p);

        float c20p = __cosf(a2 + b0);
        float c20m = __cosf(a2 - b0);
        float c01p = __cosf(a0 + b1);
        float c01m = __cosf(a0 - b1);
        float z3 = fmaf(h23m * c20m, c01m, (h23p * c20p) * c01p);

        out4[idx] = make_float4(z0, z1, z2, z3);
    }
}

extern "C" void kernel_launch(void* const* d_in, const int* in_sizes, int n_in,
                              void* d_out, int out_size)
{
    const float4* x4 = (const float4*)d_in[0];   // x: (4096, 1024) f32
    const float4* w4 = (const float4*)d_in[1];   // weights: (256, 2, 4) f32
    float4* o4 = (float4*)d_out;                 // out: (4096, 1024) f32

    int total = in_sizes[0] / 4;                 // 1,048,576 sims
    int nthreads = total / SPT;                  // 262,144 (multiple of 256)
    int grid = (nthreads + QL_BDIM - 1) / QL_BDIM;
    ql_closed_kernel<<<grid, QL_BDIM>>>(x4, w4, o4, nthreads);
}

// round 9
// speedup vs baseline: 2.1845x; 1.0369x over previous
#include <cuda_runtime.h>

// QuantumLinear closed form, memory-latency-optimized.
//
// Closed form (X-basis Walsh collapse), a_q = x_q + w0_q, b_q = w1_q:
//   z0 = 1/2[cos(a1+a3)cos(a0+b3)cos(b1+b2) + cos(a1-a3)cos(a0-b3)cos(b1-b2)]
//   z1 = 1/2 cos(a3)[cos(a0+a2)cos(b0+b1) + cos(a0-a2)cos(b0-b1)]
//   z2 = 1/2 cos(b0)[cos(a1+a3)cos(b1+b2) + cos(a1-a3)cos(b1-b2)]
//   z3 = 1/2[cos(b2+b3)cos(a2+b0)cos(a0+b1) + cos(b2-b3)cos(a2-b0)cos(a0-b1)]
//
// This round: front-batch ALL global loads (4x float4 of x + 2 weight float4)
// so every warp has 6 outstanding LDGs before its first dependent use —
// DRAM latency (~577 cyc) is covered by cross-warp MLP and the kernel runs at
// the bandwidth roofline. x / out are single-use -> streaming (.cs) hints.

#define QL_BDIM 256
#define SPT 4            // sims per thread

__global__ __launch_bounds__(QL_BDIM)
void ql_closed_kernel(const float4* __restrict__ x4,
                      const float4* __restrict__ w4,
                      float4* __restrict__ out4,
                      int nthreads)          // = total_sims / SPT, multiple of 256
{
    int t = blockIdx.x * QL_BDIM + threadIdx.x;
    if (t >= nthreads) return;
    int c = t & 255;                          // circuit index, same for all SPT sims

    // ---- front-batched loads: 2 weight + SPT x-vectors, all in flight ----
    float4 w0 = w4[2 * c];
    float4 w1 = w4[2 * c + 1];
    float4 xv[SPT];
#pragma unroll
    for (int s = 0; s < SPT; s++)
        xv[s] = __ldcs(&x4[t + s * nthreads]);   // streaming: no L2 reuse

    float b0 = w1.x, b1 = w1.y, b2 = w1.z, b3 = w1.w;

    // weight-only constants (1/2 folded in)
    float h12p = 0.5f * __cosf(b1 + b2);
    float h12m = 0.5f * __cosf(b1 - b2);
    float h01p = 0.5f * __cosf(b0 + b1);
    float h01m = 0.5f * __cosf(b0 - b1);
    float cb0  = __cosf(b0);
    float g12p = cb0 * h12p;                  // for z2
    float g12m = cb0 * h12m;
    float h23p = 0.5f * __cosf(b2 + b3);
    float h23m = 0.5f * __cosf(b2 - b3);

#pragma unroll
    for (int s = 0; s < SPT; s++) {
        float a0 = xv[s].x + w0.x;
        float a1 = xv[s].y + w0.y;
        float a2 = xv[s].z + w0.z;
        float a3 = xv[s].w + w0.w;

        float ca13p = __cosf(a1 + a3);
        float ca13m = __cosf(a1 - a3);

        float c0p = __cosf(a0 + b3);
        float c0m = __cosf(a0 - b3);
        float z0 = fmaf(ca13m * c0m, h12m, (ca13p * c0p) * h12p);

        float ca3  = __cosf(a3);
        float c02p = __cosf(a0 + a2);
        float c02m = __cosf(a0 - a2);
        float z1 = ca3 * fmaf(c02m, h01m, c02p * h01p);

        float z2 = fmaf(ca13m, g12m, ca13p * g12p);

        float c20p = __cosf(a2 + b0);
        float c20m = __cosf(a2 - b0);
        float c01p = __cosf(a0 + b1);
        float c01m = __cosf(a0 - b1);
        float z3 = fmaf(h23m * c20m, c01m, (h23p * c20p) * c01p);

        __stcs(&out4[t + s * nthreads], make_float4(z0, z1, z2, z3));
    }
}

extern "C" void kernel_launch(void* const* d_in, const int* in_sizes, int n_in,
                              void* d_out, int out_size)
{
    const float4* x4 = (const float4*)d_in[0];   // x: (4096, 1024) f32
    const float4* w4 = (const float4*)d_in[1];   // weights: (256, 2, 4) f32
    float4* o4 = (float4*)d_out;                 // out: (4096, 1024) f32

    int total = in_sizes[0] / 4;                 // 1,048,576 sims
    int nthreads = total / SPT;                  // 262,144 (multiple of 256)
    int grid = (nthreads + QL_BDIM - 1) / QL_BDIM;
    ql_closed_kernel<<<grid, QL_BDIM>>>(x4, w4, o4, nthreads);
}